// round 1
// baseline (speedup 1.0000x reference)
#include <cuda_runtime.h>
#include <math.h>

#define B_ 8
#define C_ 512
#define N_ 4096
#define M_ 64
#define EPS_ 1e-6f
#define NSPLIT 8

// Scratch (static device globals: allowed; runtime alloc is not)
__device__ float d_QS[B_*M_*N_];                 // softplus(Q)  [B][M][N]  8 MB
__device__ float d_KS[B_*M_*N_];                 // softplus(K)  [B][M][N]  8 MB
__device__ float d_V [(size_t)B_*C_*N_];         // gated V      [B][C][N] 64 MB
__device__ float d_gate[B_*C_];
__device__ float d_KVp[(size_t)NSPLIT*B_*M_*C_]; // split-N partials
__device__ float d_KV [B_*M_*C_];                // [B][M][C]
__device__ float d_sumK[B_*M_];
__device__ float d_norm[B_*N_];

__device__ __forceinline__ float softplus_f(float v) {
    // log(1+exp(v)), stable
    return fmaxf(v, 0.f) + log1pf(expf(-fabsf(v)));
}

// ---------------------------------------------------------------------------
// gate[b,c] = max_n x[b,c,n] + mean_n x[b,c,n]
// ---------------------------------------------------------------------------
__global__ void gate_kernel(const float* __restrict__ x) {
    int bc = blockIdx.x;
    const float* p = x + (size_t)bc * N_;
    float mx = -3.4e38f, sm = 0.f;
    for (int i = threadIdx.x; i < N_; i += 256) {
        float v = p[i];
        mx = fmaxf(mx, v); sm += v;
    }
    __shared__ float smx[8], ssm[8];
    #pragma unroll
    for (int o = 16; o; o >>= 1) {
        mx = fmaxf(mx, __shfl_xor_sync(0xffffffffu, mx, o));
        sm += __shfl_xor_sync(0xffffffffu, sm, o);
    }
    int w = threadIdx.x >> 5, l = threadIdx.x & 31;
    if (l == 0) { smx[w] = mx; ssm[w] = sm; }
    __syncthreads();
    if (threadIdx.x < 32) {
        mx = (l < 8) ? smx[l] : -3.4e38f;
        sm = (l < 8) ? ssm[l] : 0.f;
        #pragma unroll
        for (int o = 4; o; o >>= 1) {
            mx = fmaxf(mx, __shfl_xor_sync(0xffffffffu, mx, o));
            sm += __shfl_xor_sync(0xffffffffu, sm, o);
        }
        if (l == 0) d_gate[bc] = mx + sm * (1.f / N_);
    }
}

// ---------------------------------------------------------------------------
// Fused QKV GEMM over stacked rows [640 = 64 Q | 64 K | 512 V] x [C=512] @ x[b]
// 128x128 block tile, 8x8 micro-tile, k-chunk 8.
// Epilogue: softplus for Q/K rows, gate*(.+bias) for V rows.
// ---------------------------------------------------------------------------
__global__ __launch_bounds__(256) void qkv_kernel(
    const float* __restrict__ x,
    const float* __restrict__ wq, const float* __restrict__ bq,
    const float* __restrict__ wk, const float* __restrict__ bk,
    const float* __restrict__ wv, const float* __restrict__ bv)
{
    __shared__ float As[8][132];   // [k][row]
    __shared__ float Bs[8][132];   // [k][n]
    int n0 = blockIdx.x * 128;
    int r0 = blockIdx.y * 128;
    int b  = blockIdx.z;
    const float* xb = x + (size_t)b * C_ * N_;
    int t  = threadIdx.x;
    int tx = t & 15, ty = t >> 4;

    float acc[8][8];
    #pragma unroll
    for (int i = 0; i < 8; i++)
        #pragma unroll
        for (int j = 0; j < 8; j++) acc[i][j] = 0.f;

    int lkk = t & 7,   lrr = t >> 3;   // A-tile loader coords
    int lnn = t & 127, lk0 = t >> 7;   // B-tile loader coords

    // weight row base pointers for the 4 rows this thread loads
    const float* wptr[4];
    #pragma unroll
    for (int i = 0; i < 4; i++) {
        int gr = r0 + lrr + 32 * i;
        if (gr < 64)        wptr[i] = wq + (size_t)gr        * C_;
        else if (gr < 128)  wptr[i] = wk + (size_t)(gr - 64) * C_;
        else                wptr[i] = wv + (size_t)(gr - 128)* C_;
    }

    for (int k0 = 0; k0 < C_; k0 += 8) {
        #pragma unroll
        for (int i = 0; i < 4; i++)
            As[lkk][lrr + 32 * i] = wptr[i][k0 + lkk];
        #pragma unroll
        for (int i = 0; i < 4; i++) {
            int kk = lk0 + 2 * i;
            Bs[kk][lnn] = xb[(size_t)(k0 + kk) * N_ + n0 + lnn];
        }
        __syncthreads();
        #pragma unroll
        for (int kk = 0; kk < 8; kk++) {
            float4 a0 = *(const float4*)&As[kk][ty * 8];
            float4 a1 = *(const float4*)&As[kk][ty * 8 + 4];
            float4 b0 = *(const float4*)&Bs[kk][tx * 8];
            float4 b1 = *(const float4*)&Bs[kk][tx * 8 + 4];
            float av[8] = {a0.x,a0.y,a0.z,a0.w,a1.x,a1.y,a1.z,a1.w};
            float bw[8] = {b0.x,b0.y,b0.z,b0.w,b1.x,b1.y,b1.z,b1.w};
            #pragma unroll
            for (int i = 0; i < 8; i++)
                #pragma unroll
                for (int j = 0; j < 8; j++)
                    acc[i][j] += av[i] * bw[j];
        }
        __syncthreads();
    }

    #pragma unroll
    for (int i = 0; i < 8; i++) {
        int gr = r0 + ty * 8 + i;
        #pragma unroll
        for (int j = 0; j < 8; j++) {
            int n = n0 + tx * 8 + j;
            float v = acc[i][j];
            if (gr < 64) {
                d_QS[((size_t)b * M_ + gr) * N_ + n] = softplus_f(v + bq[gr]);
            } else if (gr < 128) {
                int lr = gr - 64;
                d_KS[((size_t)b * M_ + lr) * N_ + n] = softplus_f(v + bk[lr]);
            } else {
                int lr = gr - 128;
                d_V[((size_t)b * C_ + lr) * N_ + n] =
                    d_gate[b * C_ + lr] * (v + bv[lr]);
            }
        }
    }
}

// ---------------------------------------------------------------------------
// KV partials: KVp[sp][b][m][c] = sum_{n in split sp} KS[b][m][n] * V[b][c][n]
// Block: m(64) x c(128) tile, reduction over its N-split in chunks of 32.
// ---------------------------------------------------------------------------
__global__ __launch_bounds__(256) void kv_kernel() {
    __shared__ float KsT[32][68];    // [nn][m]
    __shared__ float VsT[32][132];   // [nn][c]
    int c0 = blockIdx.x * 128;
    int sp = blockIdx.y;
    int b  = blockIdx.z;
    int t  = threadIdx.x;
    int tx = t & 15, ty = t >> 4;    // ty -> 4 m rows, tx -> 8 c cols
    float acc[4][8];
    #pragma unroll
    for (int i = 0; i < 4; i++)
        #pragma unroll
        for (int j = 0; j < 8; j++) acc[i][j] = 0.f;

    int lnn = t & 31, lr0 = t >> 5;  // 0..7
    int nbeg = sp * (N_ / NSPLIT);
    int nend = nbeg + (N_ / NSPLIT);

    for (int nb = nbeg; nb < nend; nb += 32) {
        #pragma unroll
        for (int i = 0; i < 8; i++) {
            int m = lr0 + 8 * i;
            KsT[lnn][m] = d_KS[((size_t)b * M_ + m) * N_ + nb + lnn];
        }
        #pragma unroll
        for (int i = 0; i < 16; i++) {
            int c = lr0 + 8 * i;
            VsT[lnn][c] = d_V[((size_t)b * C_ + c0 + c) * N_ + nb + lnn];
        }
        __syncthreads();
        #pragma unroll
        for (int nn = 0; nn < 32; nn++) {
            float4 a0 = *(const float4*)&KsT[nn][ty * 4];
            float4 b0 = *(const float4*)&VsT[nn][tx * 8];
            float4 b1 = *(const float4*)&VsT[nn][tx * 8 + 4];
            float av[4] = {a0.x,a0.y,a0.z,a0.w};
            float bw[8] = {b0.x,b0.y,b0.z,b0.w,b1.x,b1.y,b1.z,b1.w};
            #pragma unroll
            for (int i = 0; i < 4; i++)
                #pragma unroll
                for (int j = 0; j < 8; j++)
                    acc[i][j] += av[i] * bw[j];
        }
        __syncthreads();
    }
    #pragma unroll
    for (int i = 0; i < 4; i++)
        #pragma unroll
        for (int j = 0; j < 8; j++)
            d_KVp[(((size_t)sp * B_ + b) * M_ + ty * 4 + i) * C_ + c0 + tx * 8 + j]
                = acc[i][j];
}

__global__ void kv_reduce_kernel() {
    int i = blockIdx.x * 256 + threadIdx.x;
    float s = 0.f;
    #pragma unroll
    for (int sp = 0; sp < NSPLIT; sp++)
        s += d_KVp[(size_t)sp * B_ * M_ * C_ + i];
    d_KV[i] = s;
}

// sumK[b,m] = sum_n KS[b][m][n]
__global__ void sumk_kernel() {
    int bm = blockIdx.x;
    const float* p = d_KS + (size_t)bm * N_;
    float s = 0.f;
    for (int i = threadIdx.x; i < N_; i += 256) s += p[i];
    __shared__ float ss[8];
    #pragma unroll
    for (int o = 16; o; o >>= 1) s += __shfl_xor_sync(0xffffffffu, s, o);
    int w = threadIdx.x >> 5, l = threadIdx.x & 31;
    if (l == 0) ss[w] = s;
    __syncthreads();
    if (threadIdx.x < 32) {
        s = (l < 8) ? ss[l] : 0.f;
        #pragma unroll
        for (int o = 4; o; o >>= 1) s += __shfl_xor_sync(0xffffffffu, s, o);
        if (l == 0) d_sumK[bm] = s;
    }
}

// norm[b,n] = 1 / sum_m QS[b][m][n] * (sumK[b][m] + EPS)
__global__ void norm_kernel() {
    __shared__ float sk[M_];
    int b = blockIdx.y;
    int n = blockIdx.x * 256 + threadIdx.x;
    if (threadIdx.x < M_) sk[threadIdx.x] = d_sumK[b * M_ + threadIdx.x] + EPS_;
    __syncthreads();
    float s = 0.f;
    #pragma unroll 8
    for (int m = 0; m < M_; m++)
        s += d_QS[((size_t)b * M_ + m) * N_ + n] * sk[m];
    d_norm[b * N_ + n] = 1.f / s;
}

// ---------------------------------------------------------------------------
// out[b,c,n] = x[b,c,n] + gamma * norm[b,n] * sum_m QS[b][m][n] * KV[b][m][c]
// Block: c(128) x n(128), k-chunks of 32 over m.
// ---------------------------------------------------------------------------
__global__ __launch_bounds__(256) void out_kernel(const float* __restrict__ x,
                                                  const float* __restrict__ gamma,
                                                  float* __restrict__ out) {
    __shared__ float KVs[32][132];   // [m][c]
    __shared__ float Qs[32][132];    // [m][n]
    int n0 = blockIdx.x * 128;
    int c0 = blockIdx.y * 128;
    int b  = blockIdx.z;
    int t  = threadIdx.x, tx = t & 15, ty = t >> 4;
    float acc[8][8];
    #pragma unroll
    for (int i = 0; i < 8; i++)
        #pragma unroll
        for (int j = 0; j < 8; j++) acc[i][j] = 0.f;

    int lnn = t & 127, lm0 = t >> 7;
    for (int m0 = 0; m0 < M_; m0 += 32) {
        #pragma unroll
        for (int i = 0; i < 16; i++) {
            int mm = lm0 + 2 * i;
            KVs[mm][lnn] = d_KV[((size_t)b * M_ + m0 + mm) * C_ + c0 + lnn];
            Qs[mm][lnn]  = d_QS[((size_t)b * M_ + m0 + mm) * N_ + n0 + lnn];
        }
        __syncthreads();
        #pragma unroll
        for (int mm = 0; mm < 32; mm++) {
            float4 a0 = *(const float4*)&KVs[mm][ty * 8];
            float4 a1 = *(const float4*)&KVs[mm][ty * 8 + 4];
            float4 b0 = *(const float4*)&Qs[mm][tx * 8];
            float4 b1 = *(const float4*)&Qs[mm][tx * 8 + 4];
            float av[8] = {a0.x,a0.y,a0.z,a0.w,a1.x,a1.y,a1.z,a1.w};
            float bw[8] = {b0.x,b0.y,b0.z,b0.w,b1.x,b1.y,b1.z,b1.w};
            #pragma unroll
            for (int i = 0; i < 8; i++)
                #pragma unroll
                for (int j = 0; j < 8; j++)
                    acc[i][j] += av[i] * bw[j];
        }
        __syncthreads();
    }
    float g = gamma[0];
    float nrm[8];
    #pragma unroll
    for (int j = 0; j < 8; j++)
        nrm[j] = d_norm[b * N_ + n0 + tx * 8 + j] * g;
    #pragma unroll
    for (int i = 0; i < 8; i++)
        #pragma unroll
        for (int j = 0; j < 8; j++) {
            size_t o = ((size_t)b * C_ + c0 + ty * 8 + i) * N_ + n0 + tx * 8 + j;
            out[o] = x[o] + nrm[j] * acc[i][j];
        }
}

// ---------------------------------------------------------------------------
extern "C" void kernel_launch(void* const* d_in, const int* in_sizes, int n_in,
                              void* d_out, int out_size) {
    const float* x     = (const float*)d_in[0];
    const float* wq    = (const float*)d_in[1];
    const float* bq    = (const float*)d_in[2];
    const float* wk    = (const float*)d_in[3];
    const float* bk    = (const float*)d_in[4];
    const float* wv    = (const float*)d_in[5];
    const float* bv    = (const float*)d_in[6];
    const float* gamma = (const float*)d_in[7];
    float* out = (float*)d_out;

    gate_kernel<<<B_ * C_, 256>>>(x);
    qkv_kernel<<<dim3(N_ / 128, 5, B_), 256>>>(x, wq, bq, wk, bk, wv, bv);
    kv_kernel<<<dim3(C_ / 128, NSPLIT, B_), 256>>>();
    kv_reduce_kernel<<<(B_ * M_ * C_) / 256, 256>>>();
    sumk_kernel<<<B_ * M_, 256>>>();
    norm_kernel<<<dim3(N_ / 256, B_), 256>>>();
    out_kernel<<<dim3(N_ / 128, C_ / 128, B_), 256>>>(x, gamma, out);
}

// round 4
// speedup vs baseline: 3.3080x; 3.3080x over previous
#include <cuda_runtime.h>
#include <cuda_bf16.h>
#include <cstdint>
#include <math.h>

#define B_ 8
#define C_ 512
#define N_ 4096
#define M_ 64
#define EPS_ 1e-6f
#define NSPLIT 4
#define RTOT 640   // stacked rows: 64 Q | 64 K | 512 V

// ---------------- scratch (static device globals only) ----------------
__device__ __nv_bfloat16 d_Wb[RTOT * C_];
__device__ __nv_bfloat16 d_Xb[(size_t)B_ * C_ * N_];
__device__ __nv_bfloat16 d_QSb[B_ * M_ * N_];
__device__ __nv_bfloat16 d_KSb[B_ * M_ * N_];
__device__ __nv_bfloat16 d_Vb[(size_t)B_ * C_ * N_];
__device__ float d_gate[B_ * C_];
__device__ float d_KVp[(size_t)NSPLIT * B_ * C_ * M_];   // [sp][b][c][m]
__device__ __nv_bfloat16 d_KVTb[B_ * C_ * M_];           // [b][c][m]
__device__ float d_sumK[B_ * M_];
__device__ float d_norm[B_ * N_];

__device__ __forceinline__ float softplus_f(float v) {
    return fmaxf(v, 0.f) + log1pf(expf(-fabsf(v)));
}
__device__ __forceinline__ uint32_t smem_u32(const void* p) {
    uint32_t a;
    asm("{ .reg .u64 t; cvta.to.shared.u64 t, %1; cvt.u32.u64 %0, t; }"
        : "=r"(a) : "l"(p));
    return a;
}
__device__ __forceinline__ void ldsm_x4(uint32_t addr, uint32_t* r) {
    asm volatile("ldmatrix.sync.aligned.m8n8.x4.shared.b16 {%0,%1,%2,%3}, [%4];"
                 : "=r"(r[0]), "=r"(r[1]), "=r"(r[2]), "=r"(r[3]) : "r"(addr));
}
__device__ __forceinline__ void ldsm_x4_t(uint32_t addr, uint32_t* r) {
    asm volatile("ldmatrix.sync.aligned.m8n8.x4.trans.shared.b16 {%0,%1,%2,%3}, [%4];"
                 : "=r"(r[0]), "=r"(r[1]), "=r"(r[2]), "=r"(r[3]) : "r"(addr));
}
__device__ __forceinline__ void mma16816(float* c, const uint32_t* A, const uint32_t* B) {
    asm volatile(
        "mma.sync.aligned.m16n8k16.row.col.f32.bf16.bf16.f32 "
        "{%0,%1,%2,%3}, {%4,%5,%6,%7}, {%8,%9}, {%0,%1,%2,%3};"
        : "+f"(c[0]), "+f"(c[1]), "+f"(c[2]), "+f"(c[3])
        : "r"(A[0]), "r"(A[1]), "r"(A[2]), "r"(A[3]), "r"(B[0]), "r"(B[1]));
}
__device__ __forceinline__ __nv_bfloat162 bf2(float a, float b) {
    return __floats2bfloat162_rn(a, b);
}

// ---------------------------------------------------------------------------
// x -> bf16, fused with gate[b,c] = max_n + mean_n (exact fp32)
// ---------------------------------------------------------------------------
__global__ void convert_gate_x_kernel(const float* __restrict__ x) {
    int bc = blockIdx.x;                 // over B*C
    int t = threadIdx.x;                 // 128
    const float4* p = (const float4*)(x + (size_t)bc * N_);
    __nv_bfloat162* q = (__nv_bfloat162*)(d_Xb + (size_t)bc * N_);
    float mx = -3.4e38f, sm = 0.f;
    #pragma unroll
    for (int i = 0; i < 8; i++) {
        int idx = i * 128 + t;
        float4 v = p[idx];
        q[2 * idx]     = bf2(v.x, v.y);
        q[2 * idx + 1] = bf2(v.z, v.w);
        mx = fmaxf(mx, fmaxf(fmaxf(v.x, v.y), fmaxf(v.z, v.w)));
        sm += v.x + v.y + v.z + v.w;
    }
    __shared__ float smx[4], ssm[4];
    #pragma unroll
    for (int o = 16; o; o >>= 1) {
        mx = fmaxf(mx, __shfl_xor_sync(0xffffffffu, mx, o));
        sm += __shfl_xor_sync(0xffffffffu, sm, o);
    }
    int w = t >> 5, l = t & 31;
    if (l == 0) { smx[w] = mx; ssm[w] = sm; }
    __syncthreads();
    if (t == 0) {
        mx = fmaxf(fmaxf(smx[0], smx[1]), fmaxf(smx[2], smx[3]));
        sm = ssm[0] + ssm[1] + ssm[2] + ssm[3];
        d_gate[bc] = mx + sm * (1.f / N_);
    }
}

__global__ void convert_w_kernel(const float* __restrict__ wq,
                                 const float* __restrict__ wk,
                                 const float* __restrict__ wv) {
    int i = blockIdx.x * 256 + threadIdx.x;   // RTOT*C_
    int r = i >> 9, c = i & 511;
    float w;
    if (r < 64)        w = wq[r * C_ + c];
    else if (r < 128)  w = wk[(r - 64) * C_ + c];
    else               w = wv[(r - 128) * C_ + c];
    d_Wb[i] = __float2bfloat16(w);
}

// ---------------------------------------------------------------------------
// QKV GEMM (HMMA): D[640,4096] = W[640,512] @ x[512,4096] per batch.
// CTA: 128 rows x 128 n, K chunks of 64. 8 warps (2 row x 4 col), warp 64x32.
// ---------------------------------------------------------------------------
#define PA 72    // A smem pitch (bf16)
#define PB 136   // B smem pitch (bf16)

__global__ __launch_bounds__(256) void qkv_mma_kernel(
    const float* __restrict__ bq, const float* __restrict__ bk,
    const float* __restrict__ bv)
{
    __shared__ __nv_bfloat16 sA[128 * PA];
    __shared__ __nv_bfloat16 sB[64 * PB];
    int t = threadIdx.x, L = t & 31, wid = t >> 5;
    int wr = wid >> 2, wc = wid & 3;
    int n0 = blockIdx.x * 128, r0 = blockIdx.y * 128, b = blockIdx.z;
    uint32_t aB = smem_u32(sA), bB = smem_u32(sB);

    float acc[4][4][4];
    #pragma unroll
    for (int i = 0; i < 4; i++)
        #pragma unroll
        for (int j = 0; j < 4; j++)
            #pragma unroll
            for (int k = 0; k < 4; k++) acc[i][j][k] = 0.f;

    int lrow = (L & 7) + ((L >> 3) & 1) * 8;
    int lsel = ((L >> 4) & 1) * 8;

    for (int kc = 0; kc < 8; kc++) {
        int k0 = kc * 64;
        #pragma unroll
        for (int i = 0; i < 4; i++) {           // A: 128x64
            int idx = i * 256 + t, r = idx >> 3, s = idx & 7;
            *(float4*)(sA + r * PA + s * 8) =
                *(const float4*)(d_Wb + (size_t)(r0 + r) * C_ + k0 + s * 8);
        }
        #pragma unroll
        for (int i = 0; i < 4; i++) {           // B: 64x128
            int idx = i * 256 + t, r = idx >> 4, j = idx & 15;
            *(float4*)(sB + r * PB + j * 8) =
                *(const float4*)(d_Xb + ((size_t)(b * C_ + k0 + r)) * N_ + n0 + j * 8);
        }
        __syncthreads();
        #pragma unroll
        for (int kk = 0; kk < 4; kk++) {
            int kb = kk * 16;
            uint32_t af[4][4], bf[2][4];
            #pragma unroll
            for (int mt = 0; mt < 4; mt++) {
                int ar = wr * 64 + mt * 16 + lrow;
                ldsm_x4(aB + (uint32_t)(ar * PA + kb + lsel) * 2, af[mt]);
            }
            #pragma unroll
            for (int ng = 0; ng < 2; ng++) {
                int krow = kb + lrow;
                int cb = wc * 32 + ng * 16 + lsel;
                ldsm_x4_t(bB + (uint32_t)(krow * PB + cb) * 2, bf[ng]);
            }
            #pragma unroll
            for (int mt = 0; mt < 4; mt++)
                #pragma unroll
                for (int nt = 0; nt < 4; nt++)
                    mma16816(acc[mt][nt], af[mt], &bf[nt >> 1][(nt & 1) * 2]);
        }
        __syncthreads();
    }

    // epilogue
    #pragma unroll
    for (int mt = 0; mt < 4; mt++) {
        int gr0 = r0 + wr * 64 + mt * 16 + (L >> 2);   // and gr0+8
        #pragma unroll
        for (int nt = 0; nt < 4; nt++) {
            int col = n0 + wc * 32 + nt * 8 + 2 * (L & 3);
            float v00 = acc[mt][nt][0], v01 = acc[mt][nt][1];
            float v10 = acc[mt][nt][2], v11 = acc[mt][nt][3];
            if (r0 == 0) {
                if (gr0 < 64) {
                    float b0 = bq[gr0], b1 = bq[gr0 + 8];
                    *(__nv_bfloat162*)(d_QSb + (size_t)(b * M_ + gr0) * N_ + col) =
                        bf2(softplus_f(v00 + b0), softplus_f(v01 + b0));
                    *(__nv_bfloat162*)(d_QSb + (size_t)(b * M_ + gr0 + 8) * N_ + col) =
                        bf2(softplus_f(v10 + b1), softplus_f(v11 + b1));
                } else {
                    int m0 = gr0 - 64;
                    float b0 = bk[m0], b1 = bk[m0 + 8];
                    *(__nv_bfloat162*)(d_KSb + (size_t)(b * M_ + m0) * N_ + col) =
                        bf2(softplus_f(v00 + b0), softplus_f(v01 + b0));
                    *(__nv_bfloat162*)(d_KSb + (size_t)(b * M_ + m0 + 8) * N_ + col) =
                        bf2(softplus_f(v10 + b1), softplus_f(v11 + b1));
                }
            } else {
                int c0v = gr0 - 128;
                float g0 = d_gate[b * C_ + c0v], g1 = d_gate[b * C_ + c0v + 8];
                float b0 = bv[c0v], b1 = bv[c0v + 8];
                *(__nv_bfloat162*)(d_Vb + ((size_t)(b * C_ + c0v)) * N_ + col) =
                    bf2(g0 * (v00 + b0), g0 * (v01 + b0));
                *(__nv_bfloat162*)(d_Vb + ((size_t)(b * C_ + c0v + 8)) * N_ + col) =
                    bf2(g1 * (v10 + b1), g1 * (v11 + b1));
            }
        }
    }
}

// ---------------------------------------------------------------------------
// KV^T partials: KVp[sp][b][c][m] = sum_{n in split} V[c,n] * KS[m,n]
// CTA: 128 c x 64 m; 8 warps (4 c x 2 m), warp 32x32; k chunks of 64.
// A = V tile (plain ldmatrix), B = KS tile (plain ldmatrix from [m][n]).
// ---------------------------------------------------------------------------
__global__ __launch_bounds__(256) void kv_mma_kernel() {
    __shared__ __nv_bfloat16 sV[128 * PA];
    __shared__ __nv_bfloat16 sK[64 * PA];
    int t = threadIdx.x, L = t & 31, wid = t >> 5;
    int wr = wid >> 1, wc = wid & 1;
    int c0 = blockIdx.x * 128, sp = blockIdx.y, b = blockIdx.z;
    uint32_t vB = smem_u32(sV), kB = smem_u32(sK);

    float acc[2][4][4];
    #pragma unroll
    for (int i = 0; i < 2; i++)
        #pragma unroll
        for (int j = 0; j < 4; j++)
            #pragma unroll
            for (int k = 0; k < 4; k++) acc[i][j][k] = 0.f;

    int lrow = (L & 7) + ((L >> 3) & 1) * 8;
    int lsel = ((L >> 4) & 1) * 8;
    int browB = (L & 7) + ((L >> 4) & 1) * 8;   // B plain: row sel
    int bcolB = ((L >> 3) & 1) * 8;             // B plain: k sel

    for (int ch = 0; ch < 16; ch++) {
        int nb = sp * (N_ / NSPLIT) + ch * 64;
        #pragma unroll
        for (int i = 0; i < 4; i++) {           // V: 128x64
            int idx = i * 256 + t, r = idx >> 3, s = idx & 7;
            *(float4*)(sV + r * PA + s * 8) =
                *(const float4*)(d_Vb + ((size_t)(b * C_ + c0 + r)) * N_ + nb + s * 8);
        }
        #pragma unroll
        for (int i = 0; i < 2; i++) {           // KS: 64x64
            int idx = i * 256 + t, r = idx >> 3, s = idx & 7;
            *(float4*)(sK + r * PA + s * 8) =
                *(const float4*)(d_KSb + (size_t)(b * M_ + r) * N_ + nb + s * 8);
        }
        __syncthreads();
        #pragma unroll
        for (int kk = 0; kk < 4; kk++) {
            int kb = kk * 16;
            uint32_t af[2][4], bf[2][4];
            #pragma unroll
            for (int ct = 0; ct < 2; ct++) {
                int ar = wr * 32 + ct * 16 + lrow;
                ldsm_x4(vB + (uint32_t)(ar * PA + kb + lsel) * 2, af[ct]);
            }
            #pragma unroll
            for (int bt = 0; bt < 2; bt++) {
                int mr = wc * 32 + bt * 16 + browB;
                ldsm_x4(kB + (uint32_t)(mr * PA + kb + bcolB) * 2, bf[bt]);
            }
            #pragma unroll
            for (int ct = 0; ct < 2; ct++)
                #pragma unroll
                for (int mtile = 0; mtile < 4; mtile++)
                    mma16816(acc[ct][mtile], af[ct], &bf[mtile >> 1][(mtile & 1) * 2]);
        }
        __syncthreads();
    }
    #pragma unroll
    for (int ct = 0; ct < 2; ct++) {
        int c = c0 + wr * 32 + ct * 16 + (L >> 2);
        #pragma unroll
        for (int mtile = 0; mtile < 4; mtile++) {
            int m = wc * 32 + mtile * 8 + 2 * (L & 3);
            float* p0 = d_KVp + ((size_t)(sp * B_ + b) * C_ + c) * M_ + m;
            float* p1 = d_KVp + ((size_t)(sp * B_ + b) * C_ + c + 8) * M_ + m;
            *(float2*)p0 = make_float2(acc[ct][mtile][0], acc[ct][mtile][1]);
            *(float2*)p1 = make_float2(acc[ct][mtile][2], acc[ct][mtile][3]);
        }
    }
}

__global__ void kv_reduce_kernel() {
    int i = blockIdx.x * 256 + threadIdx.x;      // B*C*M
    float s = 0.f;
    #pragma unroll
    for (int sp = 0; sp < NSPLIT; sp++)
        s += d_KVp[(size_t)sp * B_ * C_ * M_ + i];
    d_KVTb[i] = __float2bfloat16(s);
}

__global__ void sumk_kernel() {
    int bm = blockIdx.x;
    const __nv_bfloat16* p = d_KSb + (size_t)bm * N_;
    float s = 0.f;
    for (int i = threadIdx.x; i < N_; i += 256) s += __bfloat162float(p[i]);
    __shared__ float ss[8];
    #pragma unroll
    for (int o = 16; o; o >>= 1) s += __shfl_xor_sync(0xffffffffu, s, o);
    int w = threadIdx.x >> 5, l = threadIdx.x & 31;
    if (l == 0) ss[w] = s;
    __syncthreads();
    if (threadIdx.x < 32) {
        s = (l < 8) ? ss[l] : 0.f;
        #pragma unroll
        for (int o = 4; o; o >>= 1) s += __shfl_xor_sync(0xffffffffu, s, o);
        if (l == 0) d_sumK[bm] = s;
    }
}

__global__ void norm_kernel() {
    __shared__ float sk[M_];
    int b = blockIdx.y;
    int n = blockIdx.x * 256 + threadIdx.x;
    if (threadIdx.x < M_) sk[threadIdx.x] = d_sumK[b * M_ + threadIdx.x] + EPS_;
    __syncthreads();
    float s = 0.f;
    #pragma unroll 8
    for (int m = 0; m < M_; m++)
        s += __bfloat162float(d_QSb[(size_t)(b * M_ + m) * N_ + n]) * sk[m];
    d_norm[b * N_ + n] = 1.f / s;
}

// ---------------------------------------------------------------------------
// out[b,c,n] = x + gamma*norm[n]*sum_m KVT[c,m]*QS[m,n]
// CTA: 128 c x 128 n, single k chunk (m=64). A=KVT plain, B=QS trans.
// ---------------------------------------------------------------------------
__global__ __launch_bounds__(256) void out_mma_kernel(
    const float* __restrict__ x, const float* __restrict__ gamma,
    float* __restrict__ out)
{
    __shared__ __nv_bfloat16 sA[128 * PA];
    __shared__ __nv_bfloat16 sB[64 * PB];
    int t = threadIdx.x, L = t & 31, wid = t >> 5;
    int wr = wid >> 2, wc = wid & 3;
    int n0 = blockIdx.x * 128, c0 = blockIdx.y * 128, b = blockIdx.z;
    uint32_t aB = smem_u32(sA), bB = smem_u32(sB);

    #pragma unroll
    for (int i = 0; i < 4; i++) {               // KVT: 128x64
        int idx = i * 256 + t, r = idx >> 3, s = idx & 7;
        *(float4*)(sA + r * PA + s * 8) =
            *(const float4*)(d_KVTb + (size_t)(b * C_ + c0 + r) * M_ + s * 8);
    }
    #pragma unroll
    for (int i = 0; i < 4; i++) {               // QS: 64x128
        int idx = i * 256 + t, r = idx >> 4, j = idx & 15;
        *(float4*)(sB + r * PB + j * 8) =
            *(const float4*)(d_QSb + (size_t)(b * M_ + r) * N_ + n0 + j * 8);
    }
    __syncthreads();

    float acc[4][4][4];
    #pragma unroll
    for (int i = 0; i < 4; i++)
        #pragma unroll
        for (int j = 0; j < 4; j++)
            #pragma unroll
            for (int k = 0; k < 4; k++) acc[i][j][k] = 0.f;

    int lrow = (L & 7) + ((L >> 3) & 1) * 8;
    int lsel = ((L >> 4) & 1) * 8;

    #pragma unroll
    for (int kk = 0; kk < 4; kk++) {
        int kb = kk * 16;
        uint32_t af[4][4], bf[2][4];
        #pragma unroll
        for (int mt = 0; mt < 4; mt++) {
            int ar = wr * 64 + mt * 16 + lrow;
            ldsm_x4(aB + (uint32_t)(ar * PA + kb + lsel) * 2, af[mt]);
        }
        #pragma unroll
        for (int ng = 0; ng < 2; ng++) {
            int krow = kb + lrow;
            int cb = wc * 32 + ng * 16 + lsel;
            ldsm_x4_t(bB + (uint32_t)(krow * PB + cb) * 2, bf[ng]);
        }
        #pragma unroll
        for (int mt = 0; mt < 4; mt++)
            #pragma unroll
            for (int nt = 0; nt < 4; nt++)
                mma16816(acc[mt][nt], af[mt], &bf[nt >> 1][(nt & 1) * 2]);
    }

    float g = gamma[0];
    #pragma unroll
    for (int mt = 0; mt < 4; mt++) {
        int c = c0 + wr * 64 + mt * 16 + (L >> 2);
        #pragma unroll
        for (int nt = 0; nt < 4; nt++) {
            int n = n0 + wc * 32 + nt * 8 + 2 * (L & 3);
            float nv0 = g * d_norm[b * N_ + n];
            float nv1 = g * d_norm[b * N_ + n + 1];
            size_t o0 = ((size_t)(b * C_ + c)) * N_ + n;
            size_t o1 = ((size_t)(b * C_ + c + 8)) * N_ + n;
            float2 x0 = *(const float2*)(x + o0);
            float2 x1 = *(const float2*)(x + o1);
            *(float2*)(out + o0) = make_float2(x0.x + nv0 * acc[mt][nt][0],
                                               x0.y + nv1 * acc[mt][nt][1]);
            *(float2*)(out + o1) = make_float2(x1.x + nv0 * acc[mt][nt][2],
                                               x1.y + nv1 * acc[mt][nt][3]);
        }
    }
}

// ---------------------------------------------------------------------------
extern "C" void kernel_launch(void* const* d_in, const int* in_sizes, int n_in,
                              void* d_out, int out_size) {
    const float* x     = (const float*)d_in[0];
    const float* wq    = (const float*)d_in[1];
    const float* bq    = (const float*)d_in[2];
    const float* wk    = (const float*)d_in[3];
    const float* bk    = (const float*)d_in[4];
    const float* wv    = (const float*)d_in[5];
    const float* bv    = (const float*)d_in[6];
    const float* gamma = (const float*)d_in[7];
    float* out = (float*)d_out;

    convert_w_kernel<<<(RTOT * C_) / 256, 256>>>(wq, wk, wv);
    convert_gate_x_kernel<<<B_ * C_, 128>>>(x);
    qkv_mma_kernel<<<dim3(N_ / 128, RTOT / 128, B_), 256>>>(bq, bk, bv);
    kv_mma_kernel<<<dim3(C_ / 128, NSPLIT, B_), 256>>>();
    kv_reduce_kernel<<<(B_ * C_ * M_) / 256, 256>>>();
    sumk_kernel<<<B_ * M_, 256>>>();
    norm_kernel<<<dim3(N_ / 256, B_), 256>>>();
    out_mma_kernel<<<dim3(N_ / 128, C_ / 128, B_), 256>>>(x, gamma, out);
}

// round 8
// speedup vs baseline: 4.7406x; 1.4331x over previous
#include <cuda_runtime.h>
#include <cuda_bf16.h>
#include <cstdint>
#include <math.h>

#define B_ 8
#define C_ 512
#define N_ 4096
#define M_ 64
#define EPS_ 1e-6f
#define NSPLIT 16
#define RTOT 640   // stacked rows: 64 Q | 64 K | 512 V

// ---------------- scratch (static device globals only) ----------------
__device__ __nv_bfloat16 d_Wb[RTOT * C_];
__device__ __nv_bfloat16 d_Xb[(size_t)B_ * C_ * N_];
__device__ __nv_bfloat16 d_QSb[B_ * M_ * N_];
__device__ __nv_bfloat16 d_KSb[B_ * M_ * N_];
__device__ __nv_bfloat16 d_Vb[(size_t)B_ * C_ * N_];
__device__ float d_gate[B_ * C_];
__device__ float d_KVp[(size_t)NSPLIT * B_ * C_ * M_];   // [sp][b][c][m]
__device__ __nv_bfloat16 d_KVTb[B_ * C_ * M_];           // [b][c][m]
__device__ float d_sumK[B_ * M_];
__device__ float d_norm[B_ * N_];

__device__ __forceinline__ float softplus_f(float v) {
    return fmaxf(v, 0.f) + log1pf(expf(-fabsf(v)));
}
__device__ __forceinline__ uint32_t smem_u32(const void* p) {
    uint32_t a;
    asm("{ .reg .u64 t; cvta.to.shared.u64 t, %1; cvt.u32.u64 %0, t; }"
        : "=r"(a) : "l"(p));
    return a;
}
__device__ __forceinline__ void ldsm_x4(uint32_t addr, uint32_t* r) {
    asm volatile("ldmatrix.sync.aligned.m8n8.x4.shared.b16 {%0,%1,%2,%3}, [%4];"
                 : "=r"(r[0]), "=r"(r[1]), "=r"(r[2]), "=r"(r[3]) : "r"(addr));
}
__device__ __forceinline__ void ldsm_x4_t(uint32_t addr, uint32_t* r) {
    asm volatile("ldmatrix.sync.aligned.m8n8.x4.trans.shared.b16 {%0,%1,%2,%3}, [%4];"
                 : "=r"(r[0]), "=r"(r[1]), "=r"(r[2]), "=r"(r[3]) : "r"(addr));
}
__device__ __forceinline__ void mma16816(float* c, const uint32_t* A, const uint32_t* B) {
    asm volatile(
        "mma.sync.aligned.m16n8k16.row.col.f32.bf16.bf16.f32 "
        "{%0,%1,%2,%3}, {%4,%5,%6,%7}, {%8,%9}, {%0,%1,%2,%3};"
        : "+f"(c[0]), "+f"(c[1]), "+f"(c[2]), "+f"(c[3])
        : "r"(A[0]), "r"(A[1]), "r"(A[2]), "r"(A[3]), "r"(B[0]), "r"(B[1]));
}
__device__ __forceinline__ __nv_bfloat162 bf2(float a, float b) {
    return __floats2bfloat162_rn(a, b);
}
#define CP16(dst, src) \
    asm volatile("cp.async.cg.shared.global [%0], [%1], 16;" \
                 :: "r"(dst), "l"(src) : "memory")
#define CP_COMMIT() asm volatile("cp.async.commit_group;" ::: "memory")
#define CP_WAIT0()  asm volatile("cp.async.wait_group 0;" ::: "memory")
#define CP_WAIT1()  asm volatile("cp.async.wait_group 1;" ::: "memory")

// ---------------------------------------------------------------------------
// x -> bf16, fused with gate[b,c] = max_n + mean_n (exact fp32)
// ---------------------------------------------------------------------------
__global__ void convert_gate_x_kernel(const float* __restrict__ x) {
    int bc = blockIdx.x;                 // over B*C
    int t = threadIdx.x;                 // 128
    const float4* p = (const float4*)(x + (size_t)bc * N_);
    __nv_bfloat162* q = (__nv_bfloat162*)(d_Xb + (size_t)bc * N_);
    float mx = -3.4e38f, sm = 0.f;
    #pragma unroll
    for (int i = 0; i < 8; i++) {
        int idx = i * 128 + t;
        float4 v = p[idx];
        q[2 * idx]     = bf2(v.x, v.y);
        q[2 * idx + 1] = bf2(v.z, v.w);
        mx = fmaxf(mx, fmaxf(fmaxf(v.x, v.y), fmaxf(v.z, v.w)));
        sm += v.x + v.y + v.z + v.w;
    }
    __shared__ float smx[4], ssm[4];
    #pragma unroll
    for (int o = 16; o; o >>= 1) {
        mx = fmaxf(mx, __shfl_xor_sync(0xffffffffu, mx, o));
        sm += __shfl_xor_sync(0xffffffffu, sm, o);
    }
    int w = t >> 5, l = t & 31;
    if (l == 0) { smx[w] = mx; ssm[w] = sm; }
    __syncthreads();
    if (t == 0) {
        mx = fmaxf(fmaxf(smx[0], smx[1]), fmaxf(smx[2], smx[3]));
        sm = ssm[0] + ssm[1] + ssm[2] + ssm[3];
        d_gate[bc] = mx + sm * (1.f / N_);
    }
}

__global__ void convert_w_kernel(const float* __restrict__ wq,
                                 const float* __restrict__ wk,
                                 const float* __restrict__ wv) {
    int i = blockIdx.x * 256 + threadIdx.x;   // RTOT*C_
    int r = i >> 9, c = i & 511;
    float w;
    if (r < 64)        w = wq[r * C_ + c];
    else if (r < 128)  w = wk[(r - 64) * C_ + c];
    else               w = wv[(r - 128) * C_ + c];
    d_Wb[i] = __float2bfloat16(w);
}

// ---------------------------------------------------------------------------
// QKV GEMM (HMMA): D[640,4096] = W[640,512] @ x[512,4096] per batch.
// CTA: 128 rows x 128 n, K chunks of 64, 2-stage cp.async pipeline.
// 8 warps (2 row x 4 col), warp 64x32.
// ---------------------------------------------------------------------------
#define PA 72    // A smem pitch (bf16)
#define PB 136   // B smem pitch (bf16)
#define QKV_AB ((uint32_t)(128 * PA * 2))   // bytes per A buffer
#define QKV_BB ((uint32_t)(64 * PB * 2))    // bytes per B buffer
#define QKV_SMEM (2 * (QKV_AB + QKV_BB))

__device__ __forceinline__ void qkv_issue(uint32_t aAddr, uint32_t bAddr,
                                          int t, int r0, int b, int n0, int k0) {
    #pragma unroll
    for (int i = 0; i < 4; i++) {
        int idx = i * 256 + t, r = idx >> 3, s = idx & 7;
        CP16(aAddr + (uint32_t)(r * PA + s * 8) * 2,
             d_Wb + (size_t)(r0 + r) * C_ + k0 + s * 8);
    }
    #pragma unroll
    for (int i = 0; i < 4; i++) {
        int idx = i * 256 + t, r = idx >> 4, j = idx & 15;
        CP16(bAddr + (uint32_t)(r * PB + j * 8) * 2,
             d_Xb + ((size_t)(b * C_ + k0 + r)) * N_ + n0 + j * 8);
    }
}

__global__ __launch_bounds__(256) void qkv_mma_kernel(
    const float* __restrict__ bq, const float* __restrict__ bk,
    const float* __restrict__ bv)
{
    extern __shared__ __nv_bfloat16 qsm[];
    int t = threadIdx.x, L = t & 31, wid = t >> 5;
    int wr = wid >> 2, wc = wid & 3;
    int n0 = blockIdx.x * 128, r0 = blockIdx.y * 128, b = blockIdx.z;
    uint32_t base = smem_u32(qsm);
    uint32_t aA[2] = {base, base + QKV_AB};
    uint32_t bA[2] = {base + 2 * QKV_AB, base + 2 * QKV_AB + QKV_BB};

    float acc[4][4][4];
    #pragma unroll
    for (int i = 0; i < 4; i++)
        #pragma unroll
        for (int j = 0; j < 4; j++)
            #pragma unroll
            for (int k = 0; k < 4; k++) acc[i][j][k] = 0.f;

    int lrow = (L & 7) + ((L >> 3) & 1) * 8;
    int lsel = ((L >> 4) & 1) * 8;

    qkv_issue(aA[0], bA[0], t, r0, b, n0, 0);
    CP_COMMIT();

    for (int kc = 0; kc < 8; kc++) {
        if (kc < 7) {
            qkv_issue(aA[(kc + 1) & 1], bA[(kc + 1) & 1], t, r0, b, n0,
                      (kc + 1) * 64);
            CP_COMMIT();
            CP_WAIT1();
        } else {
            CP_WAIT0();
        }
        __syncthreads();
        uint32_t aB = aA[kc & 1], bB = bA[kc & 1];
        #pragma unroll
        for (int kk = 0; kk < 4; kk++) {
            int kb = kk * 16;
            uint32_t af[4][4], bf[2][4];
            #pragma unroll
            for (int mt = 0; mt < 4; mt++) {
                int ar = wr * 64 + mt * 16 + lrow;
                ldsm_x4(aB + (uint32_t)(ar * PA + kb + lsel) * 2, af[mt]);
            }
            #pragma unroll
            for (int ng = 0; ng < 2; ng++) {
                int krow = kb + lrow;
                int cb = wc * 32 + ng * 16 + lsel;
                ldsm_x4_t(bB + (uint32_t)(krow * PB + cb) * 2, bf[ng]);
            }
            #pragma unroll
            for (int mt = 0; mt < 4; mt++)
                #pragma unroll
                for (int nt = 0; nt < 4; nt++)
                    mma16816(acc[mt][nt], af[mt], &bf[nt >> 1][(nt & 1) * 2]);
        }
        __syncthreads();
    }

    // epilogue
    #pragma unroll
    for (int mt = 0; mt < 4; mt++) {
        int gr0 = r0 + wr * 64 + mt * 16 + (L >> 2);   // and gr0+8
        #pragma unroll
        for (int nt = 0; nt < 4; nt++) {
            int col = n0 + wc * 32 + nt * 8 + 2 * (L & 3);
            float v00 = acc[mt][nt][0], v01 = acc[mt][nt][1];
            float v10 = acc[mt][nt][2], v11 = acc[mt][nt][3];
            if (r0 == 0) {
                if (gr0 < 64) {
                    float b0 = bq[gr0], b1 = bq[gr0 + 8];
                    *(__nv_bfloat162*)(d_QSb + (size_t)(b * M_ + gr0) * N_ + col) =
                        bf2(softplus_f(v00 + b0), softplus_f(v01 + b0));
                    *(__nv_bfloat162*)(d_QSb + (size_t)(b * M_ + gr0 + 8) * N_ + col) =
                        bf2(softplus_f(v10 + b1), softplus_f(v11 + b1));
                } else {
                    int m0 = gr0 - 64;
                    float b0 = bk[m0], b1 = bk[m0 + 8];
                    *(__nv_bfloat162*)(d_KSb + (size_t)(b * M_ + m0) * N_ + col) =
                        bf2(softplus_f(v00 + b0), softplus_f(v01 + b0));
                    *(__nv_bfloat162*)(d_KSb + (size_t)(b * M_ + m0 + 8) * N_ + col) =
                        bf2(softplus_f(v10 + b1), softplus_f(v11 + b1));
                }
            } else {
                int c0v = gr0 - 128;
                float g0 = d_gate[b * C_ + c0v], g1 = d_gate[b * C_ + c0v + 8];
                float b0 = bv[c0v], b1 = bv[c0v + 8];
                *(__nv_bfloat162*)(d_Vb + ((size_t)(b * C_ + c0v)) * N_ + col) =
                    bf2(g0 * (v00 + b0), g0 * (v01 + b0));
                *(__nv_bfloat162*)(d_Vb + ((size_t)(b * C_ + c0v + 8)) * N_ + col) =
                    bf2(g1 * (v10 + b1), g1 * (v11 + b1));
            }
        }
    }
}

// ---------------------------------------------------------------------------
// KV^T partials: KVp[sp][b][c][m] = sum_{n in split} V[c,n] * KS[m,n]
// NSPLIT=16 -> 512 CTAs (was 128: grid starvation). Split = 256 n = 4 chunks.
// CTA: 128 c x 64 m; 8 warps (4 c x 2 m), warp 32x32.
// ---------------------------------------------------------------------------
__global__ __launch_bounds__(256) void kv_mma_kernel() {
    __shared__ __nv_bfloat16 sV[128 * PA];
    __shared__ __nv_bfloat16 sK[64 * PA];
    int t = threadIdx.x, L = t & 31, wid = t >> 5;
    int wr = wid >> 1, wc = wid & 1;
    int c0 = blockIdx.x * 128, sp = blockIdx.y, b = blockIdx.z;
    uint32_t vB = smem_u32(sV), kB = smem_u32(sK);

    float acc[2][4][4];
    #pragma unroll
    for (int i = 0; i < 2; i++)
        #pragma unroll
        for (int j = 0; j < 4; j++)
            #pragma unroll
            for (int k = 0; k < 4; k++) acc[i][j][k] = 0.f;

    int lrow = (L & 7) + ((L >> 3) & 1) * 8;
    int lsel = ((L >> 4) & 1) * 8;
    int browB = (L & 7) + ((L >> 4) & 1) * 8;
    int bcolB = ((L >> 3) & 1) * 8;

    for (int ch = 0; ch < (N_ / NSPLIT) / 64; ch++) {
        int nb = sp * (N_ / NSPLIT) + ch * 64;
        #pragma unroll
        for (int i = 0; i < 4; i++) {           // V: 128x64
            int idx = i * 256 + t, r = idx >> 3, s = idx & 7;
            CP16(vB + (uint32_t)(r * PA + s * 8) * 2,
                 d_Vb + ((size_t)(b * C_ + c0 + r)) * N_ + nb + s * 8);
        }
        #pragma unroll
        for (int i = 0; i < 2; i++) {           // KS: 64x64
            int idx = i * 256 + t, r = idx >> 3, s = idx & 7;
            CP16(kB + (uint32_t)(r * PA + s * 8) * 2,
                 d_KSb + (size_t)(b * M_ + r) * N_ + nb + s * 8);
        }
        CP_COMMIT();
        CP_WAIT0();
        __syncthreads();
        #pragma unroll
        for (int kk = 0; kk < 4; kk++) {
            int kb = kk * 16;
            uint32_t af[2][4], bf[2][4];
            #pragma unroll
            for (int ct = 0; ct < 2; ct++) {
                int ar = wr * 32 + ct * 16 + lrow;
                ldsm_x4(vB + (uint32_t)(ar * PA + kb + lsel) * 2, af[ct]);
            }
            #pragma unroll
            for (int bt = 0; bt < 2; bt++) {
                int mr = wc * 32 + bt * 16 + browB;
                ldsm_x4(kB + (uint32_t)(mr * PA + kb + bcolB) * 2, bf[bt]);
            }
            #pragma unroll
            for (int ct = 0; ct < 2; ct++)
                #pragma unroll
                for (int mtile = 0; mtile < 4; mtile++)
                    mma16816(acc[ct][mtile], af[ct], &bf[mtile >> 1][(mtile & 1) * 2]);
        }
        __syncthreads();
    }
    #pragma unroll
    for (int ct = 0; ct < 2; ct++) {
        int c = c0 + wr * 32 + ct * 16 + (L >> 2);
        #pragma unroll
        for (int mtile = 0; mtile < 4; mtile++) {
            int m = wc * 32 + mtile * 8 + 2 * (L & 3);
            float* p0 = d_KVp + ((size_t)(sp * B_ + b) * C_ + c) * M_ + m;
            float* p1 = d_KVp + ((size_t)(sp * B_ + b) * C_ + c + 8) * M_ + m;
            *(float2*)p0 = make_float2(acc[ct][mtile][0], acc[ct][mtile][1]);
            *(float2*)p1 = make_float2(acc[ct][mtile][2], acc[ct][mtile][3]);
        }
    }
}

__global__ void kv_reduce_kernel() {
    int i = blockIdx.x * 256 + threadIdx.x;      // B*C*M
    float s = 0.f;
    #pragma unroll
    for (int sp = 0; sp < NSPLIT; sp++)
        s += d_KVp[(size_t)sp * B_ * C_ * M_ + i];
    d_KVTb[i] = __float2bfloat16(s);
}

__global__ void sumk_kernel() {
    int bm = blockIdx.x;
    const __nv_bfloat16* p = d_KSb + (size_t)bm * N_;
    float s = 0.f;
    for (int i = threadIdx.x; i < N_; i += 256) s += __bfloat162float(p[i]);
    __shared__ float ss[8];
    #pragma unroll
    for (int o = 16; o; o >>= 1) s += __shfl_xor_sync(0xffffffffu, s, o);
    int w = threadIdx.x >> 5, l = threadIdx.x & 31;
    if (l == 0) ss[w] = s;
    __syncthreads();
    if (threadIdx.x < 32) {
        s = (l < 8) ? ss[l] : 0.f;
        #pragma unroll
        for (int o = 4; o; o >>= 1) s += __shfl_xor_sync(0xffffffffu, s, o);
        if (l == 0) d_sumK[bm] = s;
    }
}

__global__ void norm_kernel() {
    __shared__ float sk[M_];
    int b = blockIdx.y;
    int n = blockIdx.x * 256 + threadIdx.x;
    if (threadIdx.x < M_) sk[threadIdx.x] = d_sumK[b * M_ + threadIdx.x] + EPS_;
    __syncthreads();
    float s = 0.f;
    #pragma unroll 8
    for (int m = 0; m < M_; m++)
        s += __bfloat162float(d_QSb[(size_t)(b * M_ + m) * N_ + n]) * sk[m];
    d_norm[b * N_ + n] = 1.f / s;
}

// ---------------------------------------------------------------------------
// out[b,c,n] = x + gamma*norm[n]*sum_m KVT[c,m]*QS[m,n]
// ---------------------------------------------------------------------------
__global__ __launch_bounds__(256) void out_mma_kernel(
    const float* __restrict__ x, const float* __restrict__ gamma,
    float* __restrict__ out)
{
    __shared__ __nv_bfloat16 sA[128 * PA];
    __shared__ __nv_bfloat16 sB[64 * PB];
    int t = threadIdx.x, L = t & 31, wid = t >> 5;
    int wr = wid >> 2, wc = wid & 3;
    int n0 = blockIdx.x * 128, c0 = blockIdx.y * 128, b = blockIdx.z;
    uint32_t aB = smem_u32(sA), bB = smem_u32(sB);

    #pragma unroll
    for (int i = 0; i < 4; i++) {               // KVT: 128x64
        int idx = i * 256 + t, r = idx >> 3, s = idx & 7;
        CP16(aB + (uint32_t)(r * PA + s * 8) * 2,
             d_KVTb + (size_t)(b * C_ + c0 + r) * M_ + s * 8);
    }
    #pragma unroll
    for (int i = 0; i < 4; i++) {               // QS: 64x128
        int idx = i * 256 + t, r = idx >> 4, j = idx & 15;
        CP16(bB + (uint32_t)(r * PB + j * 8) * 2,
             d_QSb + (size_t)(b * M_ + r) * N_ + n0 + j * 8);
    }
    CP_COMMIT();
    CP_WAIT0();
    __syncthreads();

    float acc[4][4][4];
    #pragma unroll
    for (int i = 0; i < 4; i++)
        #pragma unroll
        for (int j = 0; j < 4; j++)
            #pragma unroll
            for (int k = 0; k < 4; k++) acc[i][j][k] = 0.f;

    int lrow = (L & 7) + ((L >> 3) & 1) * 8;
    int lsel = ((L >> 4) & 1) * 8;

    #pragma unroll
    for (int kk = 0; kk < 4; kk++) {
        int kb = kk * 16;
        uint32_t af[4][4], bf[2][4];
        #pragma unroll
        for (int mt = 0; mt < 4; mt++) {
            int ar = wr * 64 + mt * 16 + lrow;
            ldsm_x4(aB + (uint32_t)(ar * PA + kb + lsel) * 2, af[mt]);
        }
        #pragma unroll
        for (int ng = 0; ng < 2; ng++) {
            int krow = kb + lrow;
            int cb = wc * 32 + ng * 16 + lsel;
            ldsm_x4_t(bB + (uint32_t)(krow * PB + cb) * 2, bf[ng]);
        }
        #pragma unroll
        for (int mt = 0; mt < 4; mt++)
            #pragma unroll
            for (int nt = 0; nt < 4; nt++)
                mma16816(acc[mt][nt], af[mt], &bf[nt >> 1][(nt & 1) * 2]);
    }

    float g = gamma[0];
    #pragma unroll
    for (int mt = 0; mt < 4; mt++) {
        int c = c0 + wr * 64 + mt * 16 + (L >> 2);
        #pragma unroll
        for (int nt = 0; nt < 4; nt++) {
            int n = n0 + wc * 32 + nt * 8 + 2 * (L & 3);
            float nv0 = g * d_norm[b * N_ + n];
            float nv1 = g * d_norm[b * N_ + n + 1];
            size_t o0 = ((size_t)(b * C_ + c)) * N_ + n;
            size_t o1 = ((size_t)(b * C_ + c + 8)) * N_ + n;
            float2 x0 = *(const float2*)(x + o0);
            float2 x1 = *(const float2*)(x + o1);
            *(float2*)(out + o0) = make_float2(x0.x + nv0 * acc[mt][nt][0],
                                               x0.y + nv1 * acc[mt][nt][1]);
            *(float2*)(out + o1) = make_float2(x1.x + nv0 * acc[mt][nt][2],
                                               x1.y + nv1 * acc[mt][nt][3]);
        }
    }
}

// ---------------------------------------------------------------------------
extern "C" void kernel_launch(void* const* d_in, const int* in_sizes, int n_in,
                              void* d_out, int out_size) {
    const float* x     = (const float*)d_in[0];
    const float* wq    = (const float*)d_in[1];
    const float* bq    = (const float*)d_in[2];
    const float* wk    = (const float*)d_in[3];
    const float* bk    = (const float*)d_in[4];
    const float* wv    = (const float*)d_in[5];
    const float* bv    = (const float*)d_in[6];
    const float* gamma = (const float*)d_in[7];
    float* out = (float*)d_out;

    cudaFuncSetAttribute(qkv_mma_kernel,
                         cudaFuncAttributeMaxDynamicSharedMemorySize, QKV_SMEM);

    convert_w_kernel<<<(RTOT * C_) / 256, 256>>>(wq, wk, wv);
    convert_gate_x_kernel<<<B_ * C_, 128>>>(x);
    qkv_mma_kernel<<<dim3(N_ / 128, RTOT / 128, B_), 256, QKV_SMEM>>>(bq, bk, bv);
    kv_mma_kernel<<<dim3(C_ / 128, NSPLIT, B_), 256>>>();
    kv_reduce_kernel<<<(B_ * C_ * M_) / 256, 256>>>();
    sumk_kernel<<<B_ * M_, 256>>>();
    norm_kernel<<<dim3(N_ / 256, B_), 256>>>();
    out_mma_kernel<<<dim3(N_ / 128, C_ / 128, B_), 256>>>(x, gamma, out);
}

// round 14
// speedup vs baseline: 5.0812x; 1.0719x over previous
#include <cuda_runtime.h>
#include <cuda_bf16.h>
#include <cstdint>
#include <math.h>

#define B_ 8
#define C_ 512
#define N_ 4096
#define M_ 64
#define EPS_ 1e-6f
#define NSPLIT 16
#define RTOT 640   // stacked rows: 64 Q | 64 K | 512 V

// ---------------- scratch (static device globals only) ----------------
__device__ __nv_bfloat16 d_Wb[RTOT * C_];
__device__ __nv_bfloat16 d_Xb[(size_t)B_ * C_ * N_];
__device__ __nv_bfloat16 d_QSb[B_ * M_ * N_];
__device__ __nv_bfloat16 d_KSb[B_ * M_ * N_];
__device__ __nv_bfloat16 d_Vb[(size_t)B_ * C_ * N_];
__device__ float d_gate[B_ * C_];
__device__ float d_KVp[(size_t)NSPLIT * B_ * C_ * M_];   // [sp][b][c][m]
__device__ __nv_bfloat16 d_KVTb[B_ * C_ * M_];           // [b][c][m]
__device__ float d_sumK[B_ * M_];

__device__ __forceinline__ float softplus_f(float v) {
    return fmaxf(v, 0.f) + log1pf(expf(-fabsf(v)));
}
__device__ __forceinline__ uint32_t smem_u32(const void* p) {
    uint32_t a;
    asm("{ .reg .u64 t; cvta.to.shared.u64 t, %1; cvt.u32.u64 %0, t; }"
        : "=r"(a) : "l"(p));
    return a;
}
__device__ __forceinline__ void ldsm_x4(uint32_t addr, uint32_t* r) {
    asm volatile("ldmatrix.sync.aligned.m8n8.x4.shared.b16 {%0,%1,%2,%3}, [%4];"
                 : "=r"(r[0]), "=r"(r[1]), "=r"(r[2]), "=r"(r[3]) : "r"(addr));
}
__device__ __forceinline__ void ldsm_x4_t(uint32_t addr, uint32_t* r) {
    asm volatile("ldmatrix.sync.aligned.m8n8.x4.trans.shared.b16 {%0,%1,%2,%3}, [%4];"
                 : "=r"(r[0]), "=r"(r[1]), "=r"(r[2]), "=r"(r[3]) : "r"(addr));
}
__device__ __forceinline__ void mma16816(float* c, const uint32_t* A, const uint32_t* B) {
    asm volatile(
        "mma.sync.aligned.m16n8k16.row.col.f32.bf16.bf16.f32 "
        "{%0,%1,%2,%3}, {%4,%5,%6,%7}, {%8,%9}, {%0,%1,%2,%3};"
        : "+f"(c[0]), "+f"(c[1]), "+f"(c[2]), "+f"(c[3])
        : "r"(A[0]), "r"(A[1]), "r"(A[2]), "r"(A[3]), "r"(B[0]), "r"(B[1]));
}
__device__ __forceinline__ __nv_bfloat162 bf2(float a, float b) {
    return __floats2bfloat162_rn(a, b);
}
#define CP16(dst, src) \
    asm volatile("cp.async.cg.shared.global [%0], [%1], 16;" \
                 :: "r"(dst), "l"(src) : "memory")
#define CP_COMMIT() asm volatile("cp.async.commit_group;" ::: "memory")
#define CP_WAIT0()  asm volatile("cp.async.wait_group 0;" ::: "memory")
#define CP_WAIT1()  asm volatile("cp.async.wait_group 1;" ::: "memory")

// ---------------------------------------------------------------------------
// x -> bf16, fused with gate[b,c] = max_n + mean_n (exact fp32)
// ---------------------------------------------------------------------------
__global__ void convert_gate_x_kernel(const float* __restrict__ x) {
    int bc = blockIdx.x;                 // over B*C
    int t = threadIdx.x;                 // 128
    const float4* p = (const float4*)(x + (size_t)bc * N_);
    __nv_bfloat162* q = (__nv_bfloat162*)(d_Xb + (size_t)bc * N_);
    float mx = -3.4e38f, sm = 0.f;
    #pragma unroll
    for (int i = 0; i < 8; i++) {
        int idx = i * 128 + t;
        float4 v = p[idx];
        q[2 * idx]     = bf2(v.x, v.y);
        q[2 * idx + 1] = bf2(v.z, v.w);
        mx = fmaxf(mx, fmaxf(fmaxf(v.x, v.y), fmaxf(v.z, v.w)));
        sm += v.x + v.y + v.z + v.w;
    }
    __shared__ float smx[4], ssm[4];
    #pragma unroll
    for (int o = 16; o; o >>= 1) {
        mx = fmaxf(mx, __shfl_xor_sync(0xffffffffu, mx, o));
        sm += __shfl_xor_sync(0xffffffffu, sm, o);
    }
    int w = t >> 5, l = t & 31;
    if (l == 0) { smx[w] = mx; ssm[w] = sm; }
    __syncthreads();
    if (t == 0) {
        mx = fmaxf(fmaxf(smx[0], smx[1]), fmaxf(smx[2], smx[3]));
        sm = ssm[0] + ssm[1] + ssm[2] + ssm[3];
        d_gate[bc] = mx + sm * (1.f / N_);
    }
}

__global__ void convert_w_kernel(const float* __restrict__ wq,
                                 const float* __restrict__ wk,
                                 const float* __restrict__ wv) {
    int i = blockIdx.x * 256 + threadIdx.x;   // RTOT*C_
    int r = i >> 9, c = i & 511;
    float w;
    if (r < 64)        w = wq[r * C_ + c];
    else if (r < 128)  w = wk[(r - 64) * C_ + c];
    else               w = wv[(r - 128) * C_ + c];
    d_Wb[i] = __float2bfloat16(w);
}

// ---------------------------------------------------------------------------
// QKV GEMM (HMMA): D[640,4096] = W[640,512] @ x[512,4096] per batch.
// CTA: 128 rows x 128 n, K chunks of 64, 2-stage cp.async pipeline.
// ---------------------------------------------------------------------------
#define PA 72    // A smem pitch (bf16)
#define PB 136   // B smem pitch (bf16)
#define QKV_AB ((uint32_t)(128 * PA * 2))   // bytes per A buffer
#define QKV_BB ((uint32_t)(64 * PB * 2))    // bytes per B buffer
#define QKV_SMEM (2 * (QKV_AB + QKV_BB))

__device__ __forceinline__ void qkv_issue(uint32_t aAddr, uint32_t bAddr,
                                          int t, int r0, int b, int n0, int k0) {
    #pragma unroll
    for (int i = 0; i < 4; i++) {
        int idx = i * 256 + t, r = idx >> 3, s = idx & 7;
        CP16(aAddr + (uint32_t)(r * PA + s * 8) * 2,
             d_Wb + (size_t)(r0 + r) * C_ + k0 + s * 8);
    }
    #pragma unroll
    for (int i = 0; i < 4; i++) {
        int idx = i * 256 + t, r = idx >> 4, j = idx & 15;
        CP16(bAddr + (uint32_t)(r * PB + j * 8) * 2,
             d_Xb + ((size_t)(b * C_ + k0 + r)) * N_ + n0 + j * 8);
    }
}

__global__ __launch_bounds__(256) void qkv_mma_kernel(
    const float* __restrict__ bq, const float* __restrict__ bk,
    const float* __restrict__ bv)
{
    extern __shared__ __nv_bfloat16 qsm[];
    int t = threadIdx.x, L = t & 31, wid = t >> 5;
    int wr = wid >> 2, wc = wid & 3;
    int n0 = blockIdx.x * 128, r0 = blockIdx.y * 128, b = blockIdx.z;
    uint32_t base = smem_u32(qsm);
    uint32_t aA[2] = {base, base + QKV_AB};
    uint32_t bA[2] = {base + 2 * QKV_AB, base + 2 * QKV_AB + QKV_BB};

    float acc[4][4][4];
    #pragma unroll
    for (int i = 0; i < 4; i++)
        #pragma unroll
        for (int j = 0; j < 4; j++)
            #pragma unroll
            for (int k = 0; k < 4; k++) acc[i][j][k] = 0.f;

    int lrow = (L & 7) + ((L >> 3) & 1) * 8;
    int lsel = ((L >> 4) & 1) * 8;

    qkv_issue(aA[0], bA[0], t, r0, b, n0, 0);
    CP_COMMIT();

    for (int kc = 0; kc < 8; kc++) {
        if (kc < 7) {
            qkv_issue(aA[(kc + 1) & 1], bA[(kc + 1) & 1], t, r0, b, n0,
                      (kc + 1) * 64);
            CP_COMMIT();
            CP_WAIT1();
        } else {
            CP_WAIT0();
        }
        __syncthreads();
        uint32_t aB = aA[kc & 1], bB = bA[kc & 1];
        #pragma unroll
        for (int kk = 0; kk < 4; kk++) {
            int kb = kk * 16;
            uint32_t af[4][4], bf[2][4];
            #pragma unroll
            for (int mt = 0; mt < 4; mt++) {
                int ar = wr * 64 + mt * 16 + lrow;
                ldsm_x4(aB + (uint32_t)(ar * PA + kb + lsel) * 2, af[mt]);
            }
            #pragma unroll
            for (int ng = 0; ng < 2; ng++) {
                int krow = kb + lrow;
                int cb = wc * 32 + ng * 16 + lsel;
                ldsm_x4_t(bB + (uint32_t)(krow * PB + cb) * 2, bf[ng]);
            }
            #pragma unroll
            for (int mt = 0; mt < 4; mt++)
                #pragma unroll
                for (int nt = 0; nt < 4; nt++)
                    mma16816(acc[mt][nt], af[mt], &bf[nt >> 1][(nt & 1) * 2]);
        }
        __syncthreads();
    }

    // epilogue
    #pragma unroll
    for (int mt = 0; mt < 4; mt++) {
        int gr0 = r0 + wr * 64 + mt * 16 + (L >> 2);   // and gr0+8
        #pragma unroll
        for (int nt = 0; nt < 4; nt++) {
            int col = n0 + wc * 32 + nt * 8 + 2 * (L & 3);
            float v00 = acc[mt][nt][0], v01 = acc[mt][nt][1];
            float v10 = acc[mt][nt][2], v11 = acc[mt][nt][3];
            if (r0 == 0) {
                if (gr0 < 64) {
                    float b0 = bq[gr0], b1 = bq[gr0 + 8];
                    *(__nv_bfloat162*)(d_QSb + (size_t)(b * M_ + gr0) * N_ + col) =
                        bf2(softplus_f(v00 + b0), softplus_f(v01 + b0));
                    *(__nv_bfloat162*)(d_QSb + (size_t)(b * M_ + gr0 + 8) * N_ + col) =
                        bf2(softplus_f(v10 + b1), softplus_f(v11 + b1));
                } else {
                    int m0 = gr0 - 64;
                    float b0 = bk[m0], b1 = bk[m0 + 8];
                    *(__nv_bfloat162*)(d_KSb + (size_t)(b * M_ + m0) * N_ + col) =
                        bf2(softplus_f(v00 + b0), softplus_f(v01 + b0));
                    *(__nv_bfloat162*)(d_KSb + (size_t)(b * M_ + m0 + 8) * N_ + col) =
                        bf2(softplus_f(v10 + b1), softplus_f(v11 + b1));
                }
            } else {
                int c0v = gr0 - 128;
                float g0 = d_gate[b * C_ + c0v], g1 = d_gate[b * C_ + c0v + 8];
                float b0 = bv[c0v], b1 = bv[c0v + 8];
                *(__nv_bfloat162*)(d_Vb + ((size_t)(b * C_ + c0v)) * N_ + col) =
                    bf2(g0 * (v00 + b0), g0 * (v01 + b0));
                *(__nv_bfloat162*)(d_Vb + ((size_t)(b * C_ + c0v + 8)) * N_ + col) =
                    bf2(g1 * (v10 + b1), g1 * (v11 + b1));
            }
        }
    }
}

// ---------------------------------------------------------------------------
// KV^T partials: KVp[sp][b][c][m] = sum_{n in split} V[c,n] * KS[m,n]
// 512 CTAs; 2-stage cp.async double buffering (dynamic smem, 55 KB).
// CTA: 128 c x 64 m; 8 warps (4 c x 2 m), warp 32x32.
// ---------------------------------------------------------------------------
#define KV_VB ((uint32_t)(128 * PA * 2))   // bytes per V buffer
#define KV_KB ((uint32_t)(64 * PA * 2))    // bytes per K buffer
#define KV_STAGE (KV_VB + KV_KB)
#define KV_SMEM (2 * KV_STAGE)

__device__ __forceinline__ void kv_issue(uint32_t vAddr, uint32_t kAddr,
                                         int t, int c0, int b, int nb) {
    #pragma unroll
    for (int i = 0; i < 4; i++) {           // V: 128x64
        int idx = i * 256 + t, r = idx >> 3, s = idx & 7;
        CP16(vAddr + (uint32_t)(r * PA + s * 8) * 2,
             d_Vb + ((size_t)(b * C_ + c0 + r)) * N_ + nb + s * 8);
    }
    #pragma unroll
    for (int i = 0; i < 2; i++) {           // KS: 64x64
        int idx = i * 256 + t, r = idx >> 3, s = idx & 7;
        CP16(kAddr + (uint32_t)(r * PA + s * 8) * 2,
             d_KSb + (size_t)(b * M_ + r) * N_ + nb + s * 8);
    }
}

__global__ __launch_bounds__(256) void kv_mma_kernel() {
    extern __shared__ __nv_bfloat16 ksm[];
    int t = threadIdx.x, L = t & 31, wid = t >> 5;
    int wr = wid >> 1, wc = wid & 1;
    int c0 = blockIdx.x * 128, sp = blockIdx.y, b = blockIdx.z;
    uint32_t base = smem_u32(ksm);
    uint32_t vA[2] = {base, base + KV_STAGE};
    uint32_t kA[2] = {base + KV_VB, base + KV_STAGE + KV_VB};

    float acc[2][4][4];
    #pragma unroll
    for (int i = 0; i < 2; i++)
        #pragma unroll
        for (int j = 0; j < 4; j++)
            #pragma unroll
            for (int k = 0; k < 4; k++) acc[i][j][k] = 0.f;

    int lrow = (L & 7) + ((L >> 3) & 1) * 8;
    int lsel = ((L >> 4) & 1) * 8;
    int browB = (L & 7) + ((L >> 4) & 1) * 8;
    int bcolB = ((L >> 3) & 1) * 8;

    const int NCH = (N_ / NSPLIT) / 64;     // 4
    int nbase = sp * (N_ / NSPLIT);

    kv_issue(vA[0], kA[0], t, c0, b, nbase);
    CP_COMMIT();

    for (int ch = 0; ch < NCH; ch++) {
        if (ch < NCH - 1) {
            kv_issue(vA[(ch + 1) & 1], kA[(ch + 1) & 1], t, c0, b,
                     nbase + (ch + 1) * 64);
            CP_COMMIT();
            CP_WAIT1();
        } else {
            CP_WAIT0();
        }
        __syncthreads();
        uint32_t vB = vA[ch & 1], kB = kA[ch & 1];
        #pragma unroll
        for (int kk = 0; kk < 4; kk++) {
            int kb = kk * 16;
            uint32_t af[2][4], bf[2][4];
            #pragma unroll
            for (int ct = 0; ct < 2; ct++) {
                int ar = wr * 32 + ct * 16 + lrow;
                ldsm_x4(vB + (uint32_t)(ar * PA + kb + lsel) * 2, af[ct]);
            }
            #pragma unroll
            for (int bt = 0; bt < 2; bt++) {
                int mr = wc * 32 + bt * 16 + browB;
                ldsm_x4(kB + (uint32_t)(mr * PA + kb + bcolB) * 2, bf[bt]);
            }
            #pragma unroll
            for (int ct = 0; ct < 2; ct++)
                #pragma unroll
                for (int mtile = 0; mtile < 4; mtile++)
                    mma16816(acc[ct][mtile], af[ct], &bf[mtile >> 1][(mtile & 1) * 2]);
        }
        __syncthreads();
    }
    #pragma unroll
    for (int ct = 0; ct < 2; ct++) {
        int c = c0 + wr * 32 + ct * 16 + (L >> 2);
        #pragma unroll
        for (int mtile = 0; mtile < 4; mtile++) {
            int m = wc * 32 + mtile * 8 + 2 * (L & 3);
            float* p0 = d_KVp + ((size_t)(sp * B_ + b) * C_ + c) * M_ + m;
            float* p1 = d_KVp + ((size_t)(sp * B_ + b) * C_ + c + 8) * M_ + m;
            *(float2*)p0 = make_float2(acc[ct][mtile][0], acc[ct][mtile][1]);
            *(float2*)p1 = make_float2(acc[ct][mtile][2], acc[ct][mtile][3]);
        }
    }
}

__global__ void kv_reduce_kernel() {
    int i = blockIdx.x * 256 + threadIdx.x;      // B*C*M
    float s = 0.f;
    #pragma unroll
    for (int sp = 0; sp < NSPLIT; sp++)
        s += d_KVp[(size_t)sp * B_ * C_ * M_ + i];
    d_KVTb[i] = __float2bfloat16(s);
}

__global__ void sumk_kernel() {
    int bm = blockIdx.x;
    const __nv_bfloat16* p = d_KSb + (size_t)bm * N_;
    float s = 0.f;
    for (int i = threadIdx.x; i < N_; i += 256) s += __bfloat162float(p[i]);
    __shared__ float ss[8];
    #pragma unroll
    for (int o = 16; o; o >>= 1) s += __shfl_xor_sync(0xffffffffu, s, o);
    int w = threadIdx.x >> 5, l = threadIdx.x & 31;
    if (l == 0) ss[w] = s;
    __syncthreads();
    if (threadIdx.x < 32) {
        s = (l < 8) ? ss[l] : 0.f;
        #pragma unroll
        for (int o = 4; o; o >>= 1) s += __shfl_xor_sync(0xffffffffu, s, o);
        if (l == 0) d_sumK[bm] = s;
    }
}

// ---------------------------------------------------------------------------
// out[b,c,n] = x + gamma*norm[n]*sum_m KVT[c,m]*QS[m,n]
// norm fused: CTA computes norm[n] from its own QS tile + sumK (full m range).
// ---------------------------------------------------------------------------
__global__ __launch_bounds__(256) void out_mma_kernel(
    const float* __restrict__ x, const float* __restrict__ gamma,
    float* __restrict__ out)
{
    __shared__ __nv_bfloat16 sA[128 * PA];
    __shared__ __nv_bfloat16 sB[64 * PB];
    __shared__ float snorm[128];
    __shared__ float skv[M_];
    int t = threadIdx.x, L = t & 31, wid = t >> 5;
    int wr = wid >> 2, wc = wid & 3;
    int n0 = blockIdx.x * 128, c0 = blockIdx.y * 128, b = blockIdx.z;
    uint32_t aB = smem_u32(sA), bB = smem_u32(sB);

    #pragma unroll
    for (int i = 0; i < 4; i++) {               // KVT: 128x64
        int idx = i * 256 + t, r = idx >> 3, s = idx & 7;
        CP16(aB + (uint32_t)(r * PA + s * 8) * 2,
             d_KVTb + (size_t)(b * C_ + c0 + r) * M_ + s * 8);
    }
    #pragma unroll
    for (int i = 0; i < 4; i++) {               // QS: 64x128
        int idx = i * 256 + t, r = idx >> 4, j = idx & 15;
        CP16(bB + (uint32_t)(r * PB + j * 8) * 2,
             d_QSb + (size_t)(b * M_ + r) * N_ + n0 + j * 8);
    }
    if (t < M_) skv[t] = d_sumK[b * M_ + t] + EPS_;
    CP_COMMIT();
    CP_WAIT0();
    __syncthreads();

    // fused norm: snorm[j] = gamma / sum_m QS[m][n0+j] * (sumK[m]+eps)
    float g = gamma[0];
    if (t < 128) {
        float s = 0.f;
        #pragma unroll 8
        for (int m = 0; m < M_; m++)
            s += __bfloat162float(sB[m * PB + t]) * skv[m];
        snorm[t] = g / s;
    }
    __syncthreads();

    float acc[4][4][4];
    #pragma unroll
    for (int i = 0; i < 4; i++)
        #pragma unroll
        for (int j = 0; j < 4; j++)
            #pragma unroll
            for (int k = 0; k < 4; k++) acc[i][j][k] = 0.f;

    int lrow = (L & 7) + ((L >> 3) & 1) * 8;
    int lsel = ((L >> 4) & 1) * 8;

    #pragma unroll
    for (int kk = 0; kk < 4; kk++) {
        int kb = kk * 16;
        uint32_t af[4][4], bf[2][4];
        #pragma unroll
        for (int mt = 0; mt < 4; mt++) {
            int ar = wr * 64 + mt * 16 + lrow;
            ldsm_x4(aB + (uint32_t)(ar * PA + kb + lsel) * 2, af[mt]);
        }
        #pragma unroll
        for (int ng = 0; ng < 2; ng++) {
            int krow = kb + lrow;
            int cb = wc * 32 + ng * 16 + lsel;
            ldsm_x4_t(bB + (uint32_t)(krow * PB + cb) * 2, bf[ng]);
        }
        #pragma unroll
        for (int mt = 0; mt < 4; mt++)
            #pragma unroll
            for (int nt = 0; nt < 4; nt++)
                mma16816(acc[mt][nt], af[mt], &bf[nt >> 1][(nt & 1) * 2]);
    }

    #pragma unroll
    for (int mt = 0; mt < 4; mt++) {
        int c = c0 + wr * 64 + mt * 16 + (L >> 2);
        #pragma unroll
        for (int nt = 0; nt < 4; nt++) {
            int jc = wc * 32 + nt * 8 + 2 * (L & 3);
            int n = n0 + jc;
            float nv0 = snorm[jc];
            float nv1 = snorm[jc + 1];
            size_t o0 = ((size_t)(b * C_ + c)) * N_ + n;
            size_t o1 = ((size_t)(b * C_ + c + 8)) * N_ + n;
            float2 x0 = *(const float2*)(x + o0);
            float2 x1 = *(const float2*)(x + o1);
            *(float2*)(out + o0) = make_float2(x0.x + nv0 * acc[mt][nt][0],
                                               x0.y + nv1 * acc[mt][nt][1]);
            *(float2*)(out + o1) = make_float2(x1.x + nv0 * acc[mt][nt][2],
                                               x1.y + nv1 * acc[mt][nt][3]);
        }
    }
}

// ---------------------------------------------------------------------------
extern "C" void kernel_launch(void* const* d_in, const int* in_sizes, int n_in,
                              void* d_out, int out_size) {
    const float* x     = (const float*)d_in[0];
    const float* wq    = (const float*)d_in[1];
    const float* bq    = (const float*)d_in[2];
    const float* wk    = (const float*)d_in[3];
    const float* bk    = (const float*)d_in[4];
    const float* wv    = (const float*)d_in[5];
    const float* bv    = (const float*)d_in[6];
    const float* gamma = (const float*)d_in[7];
    float* out = (float*)d_out;

    cudaFuncSetAttribute(qkv_mma_kernel,
                         cudaFuncAttributeMaxDynamicSharedMemorySize, QKV_SMEM);
    cudaFuncSetAttribute(kv_mma_kernel,
                         cudaFuncAttributeMaxDynamicSharedMemorySize, KV_SMEM);

    convert_w_kernel<<<(RTOT * C_) / 256, 256>>>(wq, wk, wv);
    convert_gate_x_kernel<<<B_ * C_, 128>>>(x);
    qkv_mma_kernel<<<dim3(N_ / 128, RTOT / 128, B_), 256, QKV_SMEM>>>(bq, bk, bv);
    kv_mma_kernel<<<dim3(C_ / 128, NSPLIT, B_), 256, KV_SMEM>>>();
    kv_reduce_kernel<<<(B_ * C_ * M_) / 256, 256>>>();
    sumk_kernel<<<B_ * M_, 256>>>();
    out_mma_kernel<<<dim3(N_ / 128, C_ / 128, B_), 256>>>(x, gamma, out);
}